// round 6
// baseline (speedup 1.0000x reference)
#include <cuda_runtime.h>
#include <math.h>

#define HH 512
#define WW 512
#define RR 4
#define NIMG 64
#define NEL (NIMG*HH*WW)

// tile geometry
#define TC 32             // output cols per block
#define TR 48             // output rows per block
#define HR 56             // halo rows = TR + 2*RR
#define HC 40             // halo cols = TC + 2*RR
#define PIN 41            // scalar plane pitch (floats)
#define PIN2 41           // float2 plane pitch (float2s)
#define PH2 33            // h plane pitch (float2s)
#define NTHR 256
#define GY ((HH + TR - 1) / TR)   // 11

// Scratch (device globals: no allocation allowed)
__device__ double g_partial[2048];
__device__ float  g_invSf;
__device__ float2 g_AB[NEL];      // interleaved (A, b)

// ---- packed f32x2 helpers (pairs already adjacent in shared float2) ----
__device__ __forceinline__ unsigned long long ld2u(const float2* p) {
    return *reinterpret_cast<const unsigned long long*>(p);
}
__device__ __forceinline__ void add2(unsigned long long& a, unsigned long long b) {
    asm("add.rn.f32x2 %0, %0, %1;" : "+l"(a) : "l"(b));
}
__device__ __forceinline__ void sub2(unsigned long long& a, unsigned long long b) {
    const unsigned long long neg1 = 0xBF800000BF800000ULL;   // (-1.f, -1.f)
    asm("fma.rn.f32x2 %0, %1, %2, %0;" : "+l"(a) : "l"(b), "l"(neg1));
}
__device__ __forceinline__ float lo2(unsigned long long v) {
    return __uint_as_float((unsigned)(v & 0xFFFFFFFFULL));
}
__device__ __forceinline__ float hi2(unsigned long long v) {
    return __uint_as_float((unsigned)(v >> 32));
}

// ---------------- Stage 1: deterministic global sum of |a| + 1e-12 (fp64) ----
__global__ void k_sum_partial(const float* __restrict__ a) {
    __shared__ double wsum[8];
    const int b = blockIdx.x, t = threadIdx.x;
    const float4* p = (const float4*)(a + (size_t)b * 8192);
    double acc = 0.0;
    #pragma unroll
    for (int j = 0; j < 8; j++) {
        float4 v = p[t + j * 256];
        acc += (fabs((double)v.x) + 1e-12) + (fabs((double)v.y) + 1e-12)
             + (fabs((double)v.z) + 1e-12) + (fabs((double)v.w) + 1e-12);
    }
    #pragma unroll
    for (int o = 16; o > 0; o >>= 1) acc += __shfl_down_sync(0xffffffffu, acc, o);
    if ((t & 31) == 0) wsum[t >> 5] = acc;
    __syncthreads();
    if (t == 0) {
        double s = 0.0;
        #pragma unroll
        for (int w = 0; w < 8; w++) s += wsum[w];
        g_partial[b] = s;
    }
}

__global__ void k_sum_final() {
    __shared__ double wsum[8];
    const int t = threadIdx.x;
    double acc = 0.0;
    for (int j = t; j < 2048; j += 256) acc += g_partial[j];
    #pragma unroll
    for (int o = 16; o > 0; o >>= 1) acc += __shfl_down_sync(0xffffffffu, acc, o);
    if ((t & 31) == 0) wsum[t >> 5] = acc;
    __syncthreads();
    if (t == 0) {
        double s = 0.0;
        for (int w = 0; w < 8; w++) s += wsum[w];
        g_invSf = (float)(1.0 / s);
    }
}

// ---------------- Stage 2: fused 6-quantity box filter -> (A,b) ----------------
__global__ __launch_bounds__(NTHR) void k_stats(
    const float* __restrict__ X, const float* __restrict__ Y,
    const float* __restrict__ Wt)
{
    extern __shared__ unsigned char smem_raw[];
    float2* sXY = (float2*)smem_raw;                  // [HR*PIN2] packed (x,y)
    float*  sA  = (float*)(sXY + HR * PIN2);          // [HR*PIN]  |a|+eps
    float2* sH0 = (float2*)(sA + HR * PIN);           // (h_a,    h_a2xy)
    float2* sH1 = sH0 + HR * PH2;                     // (h_a2x,  h_ay)
    float2* sH2 = sH1 + HR * PH2;                     // (h_a2x2, h_ax)

    const int tid = threadIdx.x;
    const int img = blockIdx.z;
    const int bc  = blockIdx.x * TC;
    const int br  = blockIdx.y * TR;
    const size_t ibase = (size_t)img * (HH * WW);

    // ---- Phase A: vectorized halo load (zero outside = truncated box) ----
    #pragma unroll
    for (int it = 0; it < 3; ++it) {
        const int idx = tid + it * NTHR;
        if (idx < HR * (HC / 4)) {                 // 560 items
            const int rh = idx / (HC / 4);
            const int vq = idx % (HC / 4);
            const int gr = br - RR + rh;
            const int gc = bc - RR + vq * 4;       // multiple of 4, aligned
            float4 xv = make_float4(0.f,0.f,0.f,0.f);
            float4 yv = xv, av = xv;
            if (gr >= 0 && gr < HH && gc >= 0 && gc < WW) {
                const size_t o = ibase + (size_t)gr * WW + gc;
                xv = *(const float4*)(X  + o);
                yv = *(const float4*)(Y  + o);
                av = *(const float4*)(Wt + o);
            }
            const int sb2 = rh * PIN2 + vq * 4;
            sXY[sb2+0] = make_float2(xv.x, yv.x);
            sXY[sb2+1] = make_float2(xv.y, yv.y);
            sXY[sb2+2] = make_float2(xv.z, yv.z);
            sXY[sb2+3] = make_float2(xv.w, yv.w);
            const int sb = rh * PIN + vq * 4;
            sA[sb+0]=fabsf(av.x)+1e-12f; sA[sb+1]=fabsf(av.y)+1e-12f;
            sA[sb+2]=fabsf(av.z)+1e-12f; sA[sb+3]=fabsf(av.w)+1e-12f;
        }
    }
    __syncthreads();

    // ---- Phase B: horizontal 9-tap, sliding over 8 cols per thread ----
    if (tid < HR * 4) {                       // 224 threads
        const int rh = tid >> 2;              // 0..55  (conflict-free mapping)
        const int cg = tid & 3;               // 0..3   (8-col group)
        const int b2 = rh * PIN2 + cg * 8;
        const int bA = rh * PIN  + cg * 8;
        const int hb = rh * PH2  + cg * 8;

        float h0=0.f,h1=0.f,h2=0.f,h3=0.f,h4=0.f,h5=0.f;
        #pragma unroll
        for (int d = 0; d < 9; ++d) {
            const float2 xy = sXY[b2 + d];
            const float  av = sA [bA + d];
            const float ax = av * xy.x, a2x = ax * av;
            h0 += av; h5 += ax; h2 += a2x;
            h3 = fmaf(av,  xy.y, h3);
            h1 = fmaf(a2x, xy.y, h1);
            h4 = fmaf(a2x, xy.x, h4);
        }
        sH0[hb] = make_float2(h0, h1);
        sH1[hb] = make_float2(h2, h3);
        sH2[hb] = make_float2(h4, h5);

        #pragma unroll
        for (int s = 1; s < 8; ++s) {
            float2 xy = sXY[b2 + 8 + s];
            float  av = sA [bA + 8 + s];
            float ax = av * xy.x, a2x = ax * av;
            h0 += av; h5 += ax; h2 += a2x;
            h3 = fmaf(av,  xy.y, h3);
            h1 = fmaf(a2x, xy.y, h1);
            h4 = fmaf(a2x, xy.x, h4);
            xy = sXY[b2 + s - 1];
            av = sA [bA + s - 1];
            ax = av * xy.x; a2x = ax * av;
            h0 -= av; h5 -= ax; h2 -= a2x;
            h3 = fmaf(-av,  xy.y, h3);
            h1 = fmaf(-a2x, xy.y, h1);
            h4 = fmaf(-a2x, xy.x, h4);
            sH0[hb+s] = make_float2(h0, h1);
            sH1[hb+s] = make_float2(h2, h3);
            sH2[hb+s] = make_float2(h4, h5);
        }
    }
    __syncthreads();

    // ---- Phase C: vertical 9-tap sliding over 6 rows per thread + solve ----
    {
        const int c   = tid & 31;
        const int seg = tid >> 5;            // 0..7 -> rows seg*6 ..
        const int col = bc + c;
        const int ncl = min(col + RR, WW - 1) - max(col - RR, 0) + 1;
        const float invS = g_invSf;
        const int r0 = seg * 6;

        unsigned long long acc01 = 0, acc23 = 0, acc45 = 0;
        #pragma unroll
        for (int d = 0; d < 9; ++d) {
            const int hb = (r0 + d) * PH2 + c;
            add2(acc01, ld2u(sH0 + hb));
            add2(acc23, ld2u(sH1 + hb));
            add2(acc45, ld2u(sH2 + hb));
        }
        #pragma unroll
        for (int i = 0; i < 6; ++i) {
            const int gro = br + r0 + i;
            if (gro < HH) {
                const float a0 = lo2(acc01), a1 = hi2(acc01);
                const float a2 = lo2(acc23), a3 = hi2(acc23);
                const float a4 = lo2(acc45), a5 = hi2(acc45);
                const int nr = min(gro + RR, HH - 1) - max(gro - RR, 0) + 1;
                const float Nf  = (float)(nr * ncl);
                const float num = fmaf(-(a2 * a3), invS, a1);
                const float den = fabsf(fmaf(-(a2 * a5), invS, a4)) + Nf * 1e-8f;
                const float Av  = __fdividef(num, den);
                const float bv  = __fdividef(fmaf(-Av, a5, a3), a0);
                g_AB[ibase + (size_t)gro * WW + col] = make_float2(Av, bv);
            }
            if (i < 5) {
                const int ha = (r0 + 9 + i) * PH2 + c;
                const int hs = (r0 + i) * PH2 + c;
                add2(acc01, ld2u(sH0 + ha));  sub2(acc01, ld2u(sH0 + hs));
                add2(acc23, ld2u(sH1 + ha));  sub2(acc23, ld2u(sH1 + hs));
                add2(acc45, ld2u(sH2 + ha));  sub2(acc45, ld2u(sH2 + hs));
            }
        }
    }
}

// ---------------- Stage 3: box filter (A,b) + final blend ---------------------
__global__ __launch_bounds__(NTHR) void k_final(
    const float* __restrict__ X, float* __restrict__ out)
{
    __shared__ float2 sAB [HR * PIN2];
    __shared__ float2 sHab[HR * PH2];

    const int tid = threadIdx.x;
    const int img = blockIdx.z;
    const int bc  = blockIdx.x * TC;
    const int br  = blockIdx.y * TR;
    const size_t ibase = (size_t)img * (HH * WW);

    // Phase A: float4 = 2 pixels of (A,b); 1120 items
    #pragma unroll
    for (int it = 0; it < 5; ++it) {
        const int idx = tid + it * NTHR;
        if (idx < HR * (HC / 2)) {
            const int rh = idx / (HC / 2);
            const int vq = idx % (HC / 2);
            const int gr = br - RR + rh;
            const int gc = bc - RR + vq * 2;      // even pixel col
            float4 v = make_float4(0.f,0.f,0.f,0.f);
            if (gr >= 0 && gr < HH && gc >= 0 && gc < WW) {
                const size_t o = ibase + (size_t)gr * WW + gc;
                v = *(const float4*)(g_AB + o);
            }
            const int sb2 = rh * PIN2 + vq * 2;
            sAB[sb2+0] = make_float2(v.x, v.y);
            sAB[sb2+1] = make_float2(v.z, v.w);
        }
    }
    __syncthreads();

    // Phase B: horizontal 9-tap, sliding over 8 cols per thread (packed adds)
    if (tid < HR * 4) {                       // 224 threads
        const int rh = tid >> 2;
        const int cg = tid & 3;
        const int b2 = rh * PIN2 + cg * 8;
        const int hb = rh * PH2  + cg * 8;
        unsigned long long acc = 0;
        #pragma unroll
        for (int d = 0; d < 9; ++d) add2(acc, ld2u(sAB + b2 + d));
        *reinterpret_cast<unsigned long long*>(sHab + hb) = acc;
        #pragma unroll
        for (int s = 1; s < 8; ++s) {
            add2(acc, ld2u(sAB + b2 + 8 + s));
            sub2(acc, ld2u(sAB + b2 + s - 1));
            *reinterpret_cast<unsigned long long*>(sHab + hb + s) = acc;
        }
    }
    __syncthreads();

    // Phase C: vertical 9-tap sliding over 6 rows per thread + blend
    {
        const int c   = tid & 31;
        const int seg = tid >> 5;
        const int col = bc + c;
        const int ncl = min(col + RR, WW - 1) - max(col - RR, 0) + 1;
        const int r0 = seg * 6;

        unsigned long long acc = 0;
        #pragma unroll
        for (int d = 0; d < 9; ++d) add2(acc, ld2u(sHab + (r0 + d) * PH2 + c));
        #pragma unroll
        for (int i = 0; i < 6; ++i) {
            const int gro = br + r0 + i;
            if (gro < HH) {
                const int nr = min(gro + RR, HH - 1) - max(gro - RR, 0) + 1;
                const float rcpN = __fdividef(1.f, (float)(nr * ncl));
                const size_t o = ibase + (size_t)gro * WW + col;
                const float xv = X[o];
                out[o] = (lo2(acc) * xv + hi2(acc)) * rcpN;
            }
            if (i < 5) {
                add2(acc, ld2u(sHab + (r0 + 9 + i) * PH2 + c));
                sub2(acc, ld2u(sHab + (r0 + i) * PH2 + c));
            }
        }
    }
}

extern "C" void kernel_launch(void* const* d_in, const int* in_sizes, int n_in,
                              void* d_out, int out_size) {
    const float* x = (const float*)d_in[0];  // lr_x
    const float* y = (const float*)d_in[1];  // lr_y
    const float* a = (const float*)d_in[2];  // l_a
    float* out = (float*)d_out;

    k_sum_partial<<<2048, 256>>>(a);
    k_sum_final<<<1, 256>>>();

    const int smem_stats = (HR * PIN2 * 2 + HR * PIN + 3 * HR * PH2 * 2) * (int)sizeof(float); // 71904
    cudaFuncSetAttribute(k_stats, cudaFuncAttributeMaxDynamicSharedMemorySize, smem_stats);

    dim3 grid(WW / TC, GY, NIMG);  // 16 x 11 x 64
    k_stats<<<grid, NTHR, smem_stats>>>(x, y, a);
    k_final<<<grid, NTHR>>>(x, out);
}

// round 7
// speedup vs baseline: 1.0162x; 1.0162x over previous
#include <cuda_runtime.h>
#include <math.h>

#define HH 512
#define WW 512
#define RR 4
#define NIMG 64
#define NEL (NIMG*HH*WW)

// tile geometry (R4/R5 proven sweet spot)
#define TC 32             // output cols per block
#define TR 24             // output rows per block
#define HR 32             // halo rows
#define HC 40             // halo cols
#define PIN 41            // scalar plane pitch (floats)
#define PIN2 41           // float2 plane pitch (float2s)
#define PH2 33            // h plane pitch (float2s)
#define NTHR 256
#define GY ((HH + TR - 1) / TR)   // 22

// Scratch (device globals: no allocation allowed)
__device__ double g_partial[2048];
__device__ float  g_invSf;
__device__ float2 g_AB[NEL];      // interleaved (A, b)

// ---------------- Stage 1: deterministic global sum of |a| + 1e-12 (fp64) ----
__global__ void k_sum_partial(const float* __restrict__ a) {
    __shared__ double wsum[8];
    const int b = blockIdx.x, t = threadIdx.x;
    const float4* p = (const float4*)(a + (size_t)b * 8192);
    double acc = 0.0;
    #pragma unroll
    for (int j = 0; j < 8; j++) {
        float4 v = p[t + j * 256];
        acc += (fabs((double)v.x) + 1e-12) + (fabs((double)v.y) + 1e-12)
             + (fabs((double)v.z) + 1e-12) + (fabs((double)v.w) + 1e-12);
    }
    #pragma unroll
    for (int o = 16; o > 0; o >>= 1) acc += __shfl_down_sync(0xffffffffu, acc, o);
    if ((t & 31) == 0) wsum[t >> 5] = acc;
    __syncthreads();
    if (t == 0) {
        double s = 0.0;
        #pragma unroll
        for (int w = 0; w < 8; w++) s += wsum[w];
        g_partial[b] = s;
    }
}

__global__ void k_sum_final() {
    __shared__ double wsum[8];
    const int t = threadIdx.x;
    double acc = 0.0;
    for (int j = t; j < 2048; j += 256) acc += g_partial[j];
    #pragma unroll
    for (int o = 16; o > 0; o >>= 1) acc += __shfl_down_sync(0xffffffffu, acc, o);
    if ((t & 31) == 0) wsum[t >> 5] = acc;
    __syncthreads();
    if (t == 0) {
        double s = 0.0;
        for (int w = 0; w < 8; w++) s += wsum[w];
        g_invSf = (float)(1.0 / s);
    }
}

// ---------------- Stage 2: fused 6-quantity box filter -> (A,b) ----------------
// Phase A (256 thr): stage a and (ax, ay).  Phase B (128 thr): horizontal 9-tap,
// 8 cols/thread sliding.  Phase C (128 thr): vertical 9-tap, 6 rows/thread + solve.
__global__ __launch_bounds__(NTHR) void k_stats(
    const float* __restrict__ X, const float* __restrict__ Y,
    const float* __restrict__ Wt)
{
    __shared__ float2 sP [HR * PIN2];       // (ax, ay)
    __shared__ float  sA [HR * PIN];        // a = |a|+eps
    __shared__ float2 sH0[HR * PH2];        // (h_a,    h_a2xy)
    __shared__ float2 sH1[HR * PH2];        // (h_a2x,  h_ay)
    __shared__ float2 sH2[HR * PH2];        // (h_a2x2, h_ax)

    const int tid = threadIdx.x;
    const int img = blockIdx.z;
    const int bc  = blockIdx.x * TC;
    const int br  = blockIdx.y * TR;
    const size_t ibase = (size_t)img * (HH * WW);

    // ---- Phase A: vectorized halo load (zero outside = truncated box) ----
    #pragma unroll
    for (int it = 0; it < 2; ++it) {
        const int idx = tid + it * NTHR;
        if (idx < HR * (HC / 4)) {                 // 320 items
            const int rh = idx / (HC / 4);
            const int vq = idx % (HC / 4);
            const int gr = br - RR + rh;
            const int gc = bc - RR + vq * 4;       // multiple of 4, aligned
            float4 xv = make_float4(0.f,0.f,0.f,0.f);
            float4 yv = xv, av = xv;
            if (gr >= 0 && gr < HH && gc >= 0 && gc < WW) {
                const size_t o = ibase + (size_t)gr * WW + gc;
                xv = *(const float4*)(X  + o);
                yv = *(const float4*)(Y  + o);
                av = *(const float4*)(Wt + o);
            }
            const float a0 = fabsf(av.x)+1e-12f, a1 = fabsf(av.y)+1e-12f;
            const float a2 = fabsf(av.z)+1e-12f, a3 = fabsf(av.w)+1e-12f;
            const int sb2 = rh * PIN2 + vq * 4;
            sP[sb2+0] = make_float2(a0*xv.x, a0*yv.x);
            sP[sb2+1] = make_float2(a1*xv.y, a1*yv.y);
            sP[sb2+2] = make_float2(a2*xv.z, a2*yv.z);
            sP[sb2+3] = make_float2(a3*xv.w, a3*yv.w);
            const int sb = rh * PIN + vq * 4;
            sA[sb+0]=a0; sA[sb+1]=a1; sA[sb+2]=a2; sA[sb+3]=a3;
        }
    }
    __syncthreads();

    // ---- Phase B: horizontal 9-tap, sliding over 8 cols per thread (128 thr) ----
    if (tid < 128) {
        const int rh = tid & 31;              // warp = 32 rows -> conflict-free
        const int cg = tid >> 5;              // 0..3, 8 cols each
        const int b2 = rh * PIN2 + cg * 8;
        const int bA = rh * PIN  + cg * 8;
        const int hb = rh * PH2  + cg * 8;

        float h0=0.f,h1=0.f,h2=0.f,h3=0.f,h4=0.f,h5=0.f;
        #pragma unroll
        for (int d = 0; d < 9; ++d) {
            const float2 p = sP[b2 + d];      // (ax, ay)
            const float  a = sA[bA + d];
            h0 += a; h5 += p.x; h3 += p.y;
            h2 = fmaf(a,   p.x, h2);          // a2x
            h4 = fmaf(p.x, p.x, h4);          // a2x2
            h1 = fmaf(p.x, p.y, h1);          // a2xy
        }
        sH0[hb] = make_float2(h0, h1);
        sH1[hb] = make_float2(h2, h3);
        sH2[hb] = make_float2(h4, h5);

        #pragma unroll
        for (int s = 1; s < 8; ++s) {
            float2 p = sP[b2 + 8 + s];
            float  a = sA[bA + 8 + s];
            h0 += a; h5 += p.x; h3 += p.y;
            h2 = fmaf(a,   p.x, h2);
            h4 = fmaf(p.x, p.x, h4);
            h1 = fmaf(p.x, p.y, h1);
            p = sP[b2 + s - 1];
            a = sA[bA + s - 1];
            h0 -= a; h5 -= p.x; h3 -= p.y;
            h2 = fmaf(-a,   p.x, h2);
            h4 = fmaf(-p.x, p.x, h4);
            h1 = fmaf(-p.x, p.y, h1);
            sH0[hb+s] = make_float2(h0, h1);
            sH1[hb+s] = make_float2(h2, h3);
            sH2[hb+s] = make_float2(h4, h5);
        }
    }
    __syncthreads();

    // ---- Phase C: vertical 9-tap, sliding over 6 rows per thread + solve (128 thr) ----
    if (tid < 128) {
        const int c   = tid & 31;
        const int seg = tid >> 5;            // 0..3 -> rows seg*6 ..
        const int col = bc + c;
        const int ncl = min(col + RR, WW - 1) - max(col - RR, 0) + 1;
        const float invS = g_invSf;
        const int r0 = seg * 6;

        float a0=0.f,a1=0.f,a2=0.f,a3=0.f,a4=0.f,a5=0.f;
        #pragma unroll
        for (int d = 0; d < 9; ++d) {
            const int hb = (r0 + d) * PH2 + c;
            const float2 p = sH0[hb], q = sH1[hb], r = sH2[hb];
            a0 += p.x; a1 += p.y; a2 += q.x;
            a3 += q.y; a4 += r.x; a5 += r.y;
        }
        #pragma unroll
        for (int i = 0; i < 6; ++i) {
            const int gro = br + r0 + i;
            if (gro < HH) {
                const int nr = min(gro + RR, HH - 1) - max(gro - RR, 0) + 1;
                const float Nf  = (float)(nr * ncl);
                const float num = fmaf(-(a2 * a3), invS, a1);
                const float den = fabsf(fmaf(-(a2 * a5), invS, a4)) + Nf * 1e-8f;
                const float Av  = __fdividef(num, den);
                const float bv  = __fdividef(fmaf(-Av, a5, a3), a0);
                g_AB[ibase + (size_t)gro * WW + col] = make_float2(Av, bv);
            }
            if (i < 5) {
                const int ha = (r0 + 9 + i) * PH2 + c;
                const int hs = (r0 + i) * PH2 + c;
                const float2 pa = sH0[ha], qa = sH1[ha], ra = sH2[ha];
                const float2 ps = sH0[hs], qs = sH1[hs], rs = sH2[hs];
                a0 += pa.x - ps.x; a1 += pa.y - ps.y;
                a2 += qa.x - qs.x; a3 += qa.y - qs.y;
                a4 += ra.x - rs.x; a5 += ra.y - rs.y;
            }
        }
    }
}

// ---------------- Stage 3: box filter (A,b) + final blend ---------------------
__global__ __launch_bounds__(NTHR) void k_final(
    const float* __restrict__ X, float* __restrict__ out)
{
    __shared__ float2 sAB [HR * PIN2];
    __shared__ float2 sHab[HR * PH2];

    const int tid = threadIdx.x;
    const int img = blockIdx.z;
    const int bc  = blockIdx.x * TC;
    const int br  = blockIdx.y * TR;
    const size_t ibase = (size_t)img * (HH * WW);

    // Phase A: float4 = 2 pixels of (A,b); 640 items
    #pragma unroll
    for (int it = 0; it < 3; ++it) {
        const int idx = tid + it * NTHR;
        if (idx < HR * (HC / 2)) {
            const int rh = idx / (HC / 2);
            const int vq = idx % (HC / 2);
            const int gr = br - RR + rh;
            const int gc = bc - RR + vq * 2;      // even pixel col
            float4 v = make_float4(0.f,0.f,0.f,0.f);
            if (gr >= 0 && gr < HH && gc >= 0 && gc < WW) {
                const size_t o = ibase + (size_t)gr * WW + gc;
                v = *(const float4*)(g_AB + o);
            }
            const int sb2 = rh * PIN2 + vq * 2;
            sAB[sb2+0] = make_float2(v.x, v.y);
            sAB[sb2+1] = make_float2(v.z, v.w);
        }
    }
    __syncthreads();

    // Phase B: horizontal 9-tap, sliding over 8 cols per thread (128 thr)
    if (tid < 128) {
        const int rh = tid & 31;              // warp = 32 rows -> conflict-free
        const int cg = tid >> 5;              // 0..3, 8 cols each
        const int b2 = rh * PIN2 + cg * 8;
        const int hb = rh * PH2  + cg * 8;
        float hA = 0.f, hB = 0.f;
        #pragma unroll
        for (int d = 0; d < 9; ++d) {
            const float2 ab = sAB[b2 + d];
            hA += ab.x; hB += ab.y;
        }
        sHab[hb] = make_float2(hA, hB);
        #pragma unroll
        for (int s = 1; s < 8; ++s) {
            const float2 aa = sAB[b2 + 8 + s];
            const float2 as = sAB[b2 + s - 1];
            hA += aa.x - as.x;
            hB += aa.y - as.y;
            sHab[hb + s] = make_float2(hA, hB);
        }
    }
    __syncthreads();

    // Phase C: vertical 9-tap, 6 rows per thread + blend (128 thr)
    if (tid < 128) {
        const int c   = tid & 31;
        const int seg = tid >> 5;            // 0..3
        const int col = bc + c;
        const int ncl = min(col + RR, WW - 1) - max(col - RR, 0) + 1;
        const int r0 = seg * 6;

        float aA = 0.f, aB = 0.f;
        #pragma unroll
        for (int d = 0; d < 9; ++d) {
            const float2 h = sHab[(r0 + d) * PH2 + c];
            aA += h.x; aB += h.y;
        }
        #pragma unroll
        for (int i = 0; i < 6; ++i) {
            const int gro = br + r0 + i;
            if (gro < HH) {
                const int nr = min(gro + RR, HH - 1) - max(gro - RR, 0) + 1;
                const float rcpN = __fdividef(1.f, (float)(nr * ncl));
                const size_t o = ibase + (size_t)gro * WW + col;
                const float xv = X[o];
                out[o] = (aA * xv + aB) * rcpN;
            }
            if (i < 5) {
                const float2 ha = sHab[(r0 + 9 + i) * PH2 + c];
                const float2 hs = sHab[(r0 + i) * PH2 + c];
                aA += ha.x - hs.x;
                aB += ha.y - hs.y;
            }
        }
    }
}

extern "C" void kernel_launch(void* const* d_in, const int* in_sizes, int n_in,
                              void* d_out, int out_size) {
    const float* x = (const float*)d_in[0];  // lr_x
    const float* y = (const float*)d_in[1];  // lr_y
    const float* a = (const float*)d_in[2];  // l_a
    float* out = (float*)d_out;

    k_sum_partial<<<2048, 256>>>(a);
    k_sum_final<<<1, 256>>>();

    dim3 grid(WW / TC, GY, NIMG);  // 16 x 22 x 64
    k_stats<<<grid, NTHR>>>(x, y, a);
    k_final<<<grid, NTHR>>>(x, out);
}

// round 8
// speedup vs baseline: 1.1151x; 1.0973x over previous
#include <cuda_runtime.h>
#include <math.h>

#define HH 512
#define WW 512
#define RR 4
#define NIMG 64
#define NEL (NIMG*HH*WW)

// tile geometry: TR=32 -> no row-bound checks (512/32=16), 4-row C runs at 256 thr
#define TC 32             // output cols per block
#define TR 32             // output rows per block
#define HR 40             // halo rows
#define HC 40             // halo cols
#define PIN 41            // scalar plane pitch (floats)
#define PIN2 41           // float2 plane pitch (float2s)
#define PH2 33            // h plane pitch (float2s)
#define NTHR 256
#define GY (HH / TR)      // 16

// Scratch (device globals: no allocation allowed)
__device__ double g_partial[2048];
__device__ float  g_invSf;
__device__ float2 g_AB[NEL];      // interleaved (A, b)

// ---------------- Stage 1: deterministic global sum of |a| + 1e-12 (fp64) ----
__global__ void k_sum_partial(const float* __restrict__ a) {
    __shared__ double wsum[8];
    const int b = blockIdx.x, t = threadIdx.x;
    const float4* p = (const float4*)(a + (size_t)b * 8192);
    double acc = 0.0;
    #pragma unroll
    for (int j = 0; j < 8; j++) {
        float4 v = p[t + j * 256];
        acc += (fabs((double)v.x) + 1e-12) + (fabs((double)v.y) + 1e-12)
             + (fabs((double)v.z) + 1e-12) + (fabs((double)v.w) + 1e-12);
    }
    #pragma unroll
    for (int o = 16; o > 0; o >>= 1) acc += __shfl_down_sync(0xffffffffu, acc, o);
    if ((t & 31) == 0) wsum[t >> 5] = acc;
    __syncthreads();
    if (t == 0) {
        double s = 0.0;
        #pragma unroll
        for (int w = 0; w < 8; w++) s += wsum[w];
        g_partial[b] = s;
    }
}

__global__ void k_sum_final() {
    __shared__ double wsum[8];
    const int t = threadIdx.x;
    double acc = 0.0;
    for (int j = t; j < 2048; j += 256) acc += g_partial[j];
    #pragma unroll
    for (int o = 16; o > 0; o >>= 1) acc += __shfl_down_sync(0xffffffffu, acc, o);
    if ((t & 31) == 0) wsum[t >> 5] = acc;
    __syncthreads();
    if (t == 0) {
        double s = 0.0;
        for (int w = 0; w < 8; w++) s += wsum[w];
        g_invSf = (float)(1.0 / s);
    }
}

// ---------------- Stage 2: fused 6-quantity box filter -> (A,b) ----------------
__global__ __launch_bounds__(NTHR) void k_stats(
    const float* __restrict__ X, const float* __restrict__ Y,
    const float* __restrict__ Wt)
{
    extern __shared__ unsigned char smem_raw[];
    float2* sXY = (float2*)smem_raw;                 // [HR*PIN2] (x, y)
    float*  sA  = (float*)(sXY + HR * PIN2);         // [HR*PIN]  |a|+eps
    float2* sH0 = (float2*)(sA + HR * PIN);          // (h_a,    h_a2xy)
    float2* sH1 = sH0 + HR * PH2;                    // (h_a2x,  h_ay)
    float2* sH2 = sH1 + HR * PH2;                    // (h_a2x2, h_ax)

    const int tid = threadIdx.x;
    const int img = blockIdx.z;
    const int bc  = blockIdx.x * TC;
    const int br  = blockIdx.y * TR;
    const size_t ibase = (size_t)img * (HH * WW);

    // ---- Phase A: vectorized halo load (zero outside = truncated box) ----
    #pragma unroll
    for (int it = 0; it < 2; ++it) {
        const int idx = tid + it * NTHR;
        if (idx < HR * (HC / 4)) {                 // 400 items
            const int rh = idx / (HC / 4);
            const int vq = idx % (HC / 4);
            const int gr = br - RR + rh;
            const int gc = bc - RR + vq * 4;       // multiple of 4, aligned
            float4 xv = make_float4(0.f,0.f,0.f,0.f);
            float4 yv = xv, av = xv;
            if (gr >= 0 && gr < HH && gc >= 0 && gc < WW) {
                const size_t o = ibase + (size_t)gr * WW + gc;
                xv = *(const float4*)(X  + o);
                yv = *(const float4*)(Y  + o);
                av = *(const float4*)(Wt + o);
            }
            const int sb2 = rh * PIN2 + vq * 4;
            sXY[sb2+0] = make_float2(xv.x, yv.x);
            sXY[sb2+1] = make_float2(xv.y, yv.y);
            sXY[sb2+2] = make_float2(xv.z, yv.z);
            sXY[sb2+3] = make_float2(xv.w, yv.w);
            const int sb = rh * PIN + vq * 4;
            sA[sb+0]=fabsf(av.x)+1e-12f; sA[sb+1]=fabsf(av.y)+1e-12f;
            sA[sb+2]=fabsf(av.z)+1e-12f; sA[sb+3]=fabsf(av.w)+1e-12f;
        }
    }
    __syncthreads();

    // ---- Phase B: horizontal 9-tap, sliding over 4 cols per thread ----
    // step 1: rows 0..31 (all 256 threads); step 2: rows 32..39 (64 threads)
    #pragma unroll
    for (int step = 0; step < 2; ++step) {
        int rh, cg;
        bool act;
        if (step == 0) { rh = tid & 31;          cg = tid >> 5; act = true; }
        else           { rh = 32 + (tid & 7);    cg = tid >> 3; act = (tid < 64); }
        if (act) {
            const int b2 = rh * PIN2 + cg * 4;
            const int bA = rh * PIN  + cg * 4;
            const int hb = rh * PH2  + cg * 4;

            float h0=0.f,h1=0.f,h2=0.f,h3=0.f,h4=0.f,h5=0.f;
            #pragma unroll
            for (int d = 0; d < 9; ++d) {
                const float2 xy = sXY[b2 + d];
                const float  av = sA [bA + d];
                const float ax = av * xy.x, a2x = ax * av;
                h0 += av; h5 += ax; h2 += a2x;
                h3 = fmaf(av,  xy.y, h3);
                h1 = fmaf(a2x, xy.y, h1);
                h4 = fmaf(a2x, xy.x, h4);
            }
            sH0[hb] = make_float2(h0, h1);
            sH1[hb] = make_float2(h2, h3);
            sH2[hb] = make_float2(h4, h5);

            #pragma unroll
            for (int s = 1; s < 4; ++s) {
                float2 xy = sXY[b2 + 8 + s];
                float  av = sA [bA + 8 + s];
                float ax = av * xy.x, a2x = ax * av;
                h0 += av; h5 += ax; h2 += a2x;
                h3 = fmaf(av,  xy.y, h3);
                h1 = fmaf(a2x, xy.y, h1);
                h4 = fmaf(a2x, xy.x, h4);
                xy = sXY[b2 + s - 1];
                av = sA [bA + s - 1];
                ax = av * xy.x; a2x = ax * av;
                h0 -= av; h5 -= ax; h2 -= a2x;
                h3 = fmaf(-av,  xy.y, h3);
                h1 = fmaf(-a2x, xy.y, h1);
                h4 = fmaf(-a2x, xy.x, h4);
                sH0[hb+s] = make_float2(h0, h1);
                sH1[hb+s] = make_float2(h2, h3);
                sH2[hb+s] = make_float2(h4, h5);
            }
        }
    }
    __syncthreads();

    // ---- Phase C: vertical 9-tap, 4-row runs, all 256 threads + solve ----
    {
        const int c   = tid & 31;
        const int seg = tid >> 5;            // 0..7 -> rows seg*4 ..
        const int col = bc + c;
        const int ncl = min(col + RR, WW - 1) - max(col - RR, 0) + 1;
        const float invS = g_invSf;
        const int r0 = seg * 4;

        float a0=0.f,a1=0.f,a2=0.f,a3=0.f,a4=0.f,a5=0.f;
        #pragma unroll
        for (int d = 0; d < 9; ++d) {
            const int hb = (r0 + d) * PH2 + c;
            const float2 p = sH0[hb], q = sH1[hb], r = sH2[hb];
            a0 += p.x; a1 += p.y; a2 += q.x;
            a3 += q.y; a4 += r.x; a5 += r.y;
        }
        #pragma unroll
        for (int i = 0; i < 4; ++i) {
            const int gro = br + r0 + i;     // always < HH (512 = 16*32)
            {
                const int nr = min(gro + RR, HH - 1) - max(gro - RR, 0) + 1;
                const float Nf  = (float)(nr * ncl);
                const float num = fmaf(-(a2 * a3), invS, a1);
                const float den = fabsf(fmaf(-(a2 * a5), invS, a4)) + Nf * 1e-8f;
                const float Av  = __fdividef(num, den);
                const float bv  = __fdividef(fmaf(-Av, a5, a3), a0);
                g_AB[ibase + (size_t)gro * WW + col] = make_float2(Av, bv);
            }
            if (i < 3) {
                const int ha = (r0 + 9 + i) * PH2 + c;
                const int hs = (r0 + i) * PH2 + c;
                const float2 pa = sH0[ha], qa = sH1[ha], ra = sH2[ha];
                const float2 ps = sH0[hs], qs = sH1[hs], rs = sH2[hs];
                a0 += pa.x - ps.x; a1 += pa.y - ps.y;
                a2 += qa.x - qs.x; a3 += qa.y - qs.y;
                a4 += ra.x - rs.x; a5 += ra.y - rs.y;
            }
        }
    }
}

// ---------------- Stage 3: box filter (A,b) + final blend ---------------------
__global__ __launch_bounds__(NTHR) void k_final(
    const float* __restrict__ X, float* __restrict__ out)
{
    __shared__ float2 sAB [HR * PIN2];
    __shared__ float2 sHab[HR * PH2];

    const int tid = threadIdx.x;
    const int img = blockIdx.z;
    const int bc  = blockIdx.x * TC;
    const int br  = blockIdx.y * TR;
    const size_t ibase = (size_t)img * (HH * WW);

    // Phase A: float4 = 2 pixels of (A,b); 800 items
    #pragma unroll
    for (int it = 0; it < 4; ++it) {
        const int idx = tid + it * NTHR;
        if (idx < HR * (HC / 2)) {
            const int rh = idx / (HC / 2);
            const int vq = idx % (HC / 2);
            const int gr = br - RR + rh;
            const int gc = bc - RR + vq * 2;      // even pixel col
            float4 v = make_float4(0.f,0.f,0.f,0.f);
            if (gr >= 0 && gr < HH && gc >= 0 && gc < WW) {
                const size_t o = ibase + (size_t)gr * WW + gc;
                v = *(const float4*)(g_AB + o);
            }
            const int sb2 = rh * PIN2 + vq * 2;
            sAB[sb2+0] = make_float2(v.x, v.y);
            sAB[sb2+1] = make_float2(v.z, v.w);
        }
    }
    __syncthreads();

    // Phase B: horizontal 9-tap, 4-col runs (rows 0..31 by 256 thr, 32..39 by 64)
    #pragma unroll
    for (int step = 0; step < 2; ++step) {
        int rh, cg;
        bool act;
        if (step == 0) { rh = tid & 31;          cg = tid >> 5; act = true; }
        else           { rh = 32 + (tid & 7);    cg = tid >> 3; act = (tid < 64); }
        if (act) {
            const int b2 = rh * PIN2 + cg * 4;
            const int hb = rh * PH2  + cg * 4;
            float hA = 0.f, hB = 0.f;
            #pragma unroll
            for (int d = 0; d < 9; ++d) {
                const float2 ab = sAB[b2 + d];
                hA += ab.x; hB += ab.y;
            }
            sHab[hb] = make_float2(hA, hB);
            #pragma unroll
            for (int s = 1; s < 4; ++s) {
                const float2 aa = sAB[b2 + 8 + s];
                const float2 as = sAB[b2 + s - 1];
                hA += aa.x - as.x;
                hB += aa.y - as.y;
                sHab[hb + s] = make_float2(hA, hB);
            }
        }
    }
    __syncthreads();

    // Phase C: vertical 9-tap, 4-row runs, all 256 threads + blend
    {
        const int c   = tid & 31;
        const int seg = tid >> 5;
        const int col = bc + c;
        const int ncl = min(col + RR, WW - 1) - max(col - RR, 0) + 1;
        const int r0 = seg * 4;

        // prefetch the 4 guide pixels (overlaps the shared taps below)
        float xv[4];
        #pragma unroll
        for (int i = 0; i < 4; ++i)
            xv[i] = X[ibase + (size_t)(br + r0 + i) * WW + col];

        float aA = 0.f, aB = 0.f;
        #pragma unroll
        for (int d = 0; d < 9; ++d) {
            const float2 h = sHab[(r0 + d) * PH2 + c];
            aA += h.x; aB += h.y;
        }
        #pragma unroll
        for (int i = 0; i < 4; ++i) {
            const int gro = br + r0 + i;     // always < HH
            const int nr = min(gro + RR, HH - 1) - max(gro - RR, 0) + 1;
            const float rcpN = __fdividef(1.f, (float)(nr * ncl));
            out[ibase + (size_t)gro * WW + col] = (aA * xv[i] + aB) * rcpN;
            if (i < 3) {
                const float2 ha = sHab[(r0 + 9 + i) * PH2 + c];
                const float2 hs = sHab[(r0 + i) * PH2 + c];
                aA += ha.x - hs.x;
                aB += ha.y - hs.y;
            }
        }
    }
}

extern "C" void kernel_launch(void* const* d_in, const int* in_sizes, int n_in,
                              void* d_out, int out_size) {
    const float* x = (const float*)d_in[0];  // lr_x
    const float* y = (const float*)d_in[1];  // lr_y
    const float* a = (const float*)d_in[2];  // l_a
    float* out = (float*)d_out;

    k_sum_partial<<<2048, 256>>>(a);
    k_sum_final<<<1, 256>>>();

    const int smem_stats = (HR * PIN2 * 2 + HR * PIN + 3 * HR * PH2 * 2) * (int)sizeof(float); // 51360
    cudaFuncSetAttribute(k_stats, cudaFuncAttributeMaxDynamicSharedMemorySize, smem_stats);

    dim3 grid(WW / TC, GY, NIMG);  // 16 x 16 x 64
    k_stats<<<grid, NTHR, smem_stats>>>(x, y, a);
    k_final<<<grid, NTHR>>>(x, out);
}